// round 13
// baseline (speedup 1.0000x reference)
#include <cuda_runtime.h>
#include <cstdint>
#include <cstddef>

// ---------------------------------------------------------------------------
// RGCN (2 layers): aggregate-then-transform, GEMMs folded, final lin folded.
// Round-13:
//   - Xcat stored in mma-fragment-permuted k-order: within each 8-col group,
//     logical col k (w=k&7) sits at p = 2*(w&3) + (w>>2). The tf32 m16n8k8
//     A-fragment pair (tg, tg+4) becomes ADJACENT -> A loads are LDS.64,
//     cutting GEMM inner-loop LDS count ~33%. Permutation applied at
//     aggregation-write time; cp.async staging copies verbatim.
//   - GEMM __launch_bounds__(256) (reverted ,2 cap: suspected reg spill)
//   - zero_deg kernel replaced by cudaMemsetAsync (graph-capturable)
//   - operands pre-rounded to tf32 at producer time (no cvt in hot loop)
// tcgen05 unavailable: harness PTX targets sm_103 (no 'a').
// ---------------------------------------------------------------------------

#define NNODES 50000
#define NEDGES 1000000
#define CDIM   128
#define NREL   8
#define NRSEG  (NNODES * NREL)          // 400000 segments
#define KDIM   (CDIM * (NREL + 1))      // 1152
#define SCAN_CHUNK 1024
#define NSCAN_BLOCKS ((NRSEG + SCAN_CHUNK - 1) / SCAN_CHUNK)   // 391

// ---- scratch (device globals; no runtime allocation allowed) ----
__device__ int   g_deg[NRSEG];
__device__ int   g_off[NRSEG + 1];
__device__ int   g_cur[NRSEG];
__device__ int   g_bsum[512];
__device__ int   g_bscan[512];
__device__ int   g_esrc[NEDGES];
__device__ __align__(256) float g_xcat[(size_t)NNODES * KDIM];   // 230.4 MB (k-permuted)
__device__ __align__(256) float g_h[(size_t)NNODES * CDIM];      // 25.6 MB
__device__ __align__(256) float g_w1[KDIM * CDIM];
__device__ __align__(256) float g_w2[KDIM * CDIM];
__device__ __align__(16)  float g_b2[CDIM];

// ---------------------------------------------------------------------------
// helpers
// ---------------------------------------------------------------------------
__device__ __forceinline__ float tf32rf(float x) {   // round-to-nearest tf32
    uint32_t u;
    asm("cvt.rna.tf32.f32 %0, %1;" : "=r"(u) : "f"(x));
    return __uint_as_float(u);
}

__device__ __forceinline__ void cpa16(void* smem, const void* gmem, bool pred) {
    uint32_t s = (uint32_t)__cvta_generic_to_shared(smem);
    int sz = pred ? 16 : 0;
    asm volatile("cp.async.cg.shared.global [%0], [%1], 16, %2;\n"
                 :: "r"(s), "l"(gmem), "r"(sz));
}

__device__ __forceinline__ void mma8(float* c, const uint32_t* a, const uint32_t* b) {
    asm volatile(
        "mma.sync.aligned.m16n8k8.row.col.f32.tf32.tf32.f32 "
        "{%0,%1,%2,%3}, {%4,%5,%6,%7}, {%8,%9}, {%0,%1,%2,%3};"
        : "+f"(c[0]), "+f"(c[1]), "+f"(c[2]), "+f"(c[3])
        : "r"(a[0]), "r"(a[1]), "r"(a[2]), "r"(a[3]), "r"(b[0]), "r"(b[1]));
}

// Permuted store of one lane's float4 (logical cols 4l..4l+3) into an Xcat row.
// Offsets: base = (l>>1)*8 + (l&1); values j=0..3 go to base + 2j.
__device__ __forceinline__ void store_perm(float* row, int lane, float4 a) {
    int base = ((lane >> 1) << 3) + (lane & 1);
    row[base + 0] = a.x;
    row[base + 2] = a.y;
    row[base + 4] = a.z;
    row[base + 6] = a.w;
}

// ---------------------------------------------------------------------------
// CSR build
// ---------------------------------------------------------------------------
__global__ void hist_kernel(const int* __restrict__ dst, const int* __restrict__ et) {
    int e = blockIdx.x * blockDim.x + threadIdx.x;
    if (e >= NEDGES) return;
    atomicAdd(&g_deg[dst[e] * NREL + et[e]], 1);
}

__global__ void scan1_kernel() {
    __shared__ int sh[256];
    int t = threadIdx.x;
    int base = blockIdx.x * SCAN_CHUNK + t * 4;
    int v[4];
    int s = 0;
#pragma unroll
    for (int j = 0; j < 4; j++) {
        int idx = base + j;
        v[j] = (idx < NRSEG) ? g_deg[idx] : 0;
        s += v[j];
    }
    sh[t] = s;
    __syncthreads();
    for (int off = 1; off < 256; off <<= 1) {
        int x = (t >= off) ? sh[t - off] : 0;
        __syncthreads();
        sh[t] += x;
        __syncthreads();
    }
    int incl = sh[t];
    int run = incl - s;
    if (t == 255) g_bsum[blockIdx.x] = incl;
#pragma unroll
    for (int j = 0; j < 4; j++) {
        int idx = base + j;
        if (idx < NRSEG) g_off[idx] = run;
        run += v[j];
    }
}

__global__ void scan2_kernel() {
    __shared__ int sh[512];
    int t = threadIdx.x;
    int v = (t < NSCAN_BLOCKS) ? g_bsum[t] : 0;
    sh[t] = v;
    __syncthreads();
    for (int off = 1; off < 512; off <<= 1) {
        int x = (t >= off) ? sh[t - off] : 0;
        __syncthreads();
        sh[t] += x;
        __syncthreads();
    }
    if (t < NSCAN_BLOCKS) g_bscan[t] = sh[t] - v;
    if (t == NSCAN_BLOCKS - 1) g_off[NRSEG] = sh[t];
}

__global__ void scan3_kernel() {
    int i = blockIdx.x * blockDim.x + threadIdx.x;
    if (i >= NRSEG) return;
    int v = g_off[i] + g_bscan[i / SCAN_CHUNK];
    g_off[i] = v;
    g_cur[i] = v;
}

__global__ void fill_kernel(const int* __restrict__ src, const int* __restrict__ dst,
                            const int* __restrict__ et) {
    int e = blockIdx.x * blockDim.x + threadIdx.x;
    if (e >= NEDGES) return;
    int seg = dst[e] * NREL + et[e];
    int pos = atomicAdd(&g_cur[seg], 1);
    g_esrc[pos] = src[e];
}

// ---------------------------------------------------------------------------
// Weight builds (tf32 pre-rounded; [k][n] layout, UNpermuted — B side)
// ---------------------------------------------------------------------------
__global__ void buildw1_kernel(const float* __restrict__ W1, const float* __restrict__ root1) {
    int i = blockIdx.x * blockDim.x + threadIdx.x;
    if (i >= KDIM * CDIM) return;
    const int cut = NREL * CDIM * CDIM;
    float v = (i < cut) ? W1[i] : root1[i - cut];
    g_w1[i] = tf32rf(v);
}

__global__ void foldw2_kernel(const float* __restrict__ W2, const float* __restrict__ root2,
                              const float* __restrict__ linW) {
    __shared__ float rs[CDIM];
    int k = blockIdx.x;
    int j = threadIdx.x;
    const float* row = (k < NREL * CDIM) ? (W2 + (size_t)k * CDIM)
                                         : (root2 + (size_t)(k - NREL * CDIM) * CDIM);
    rs[j] = row[j];
    __syncthreads();
    float s = 0.f;
#pragma unroll 8
    for (int c = 0; c < CDIM; c++) s += rs[c] * linW[c * CDIM + j];
    g_w2[(size_t)k * CDIM + j] = tf32rf(s);
}

__global__ void foldb2_kernel(const float* __restrict__ b2, const float* __restrict__ linW,
                              const float* __restrict__ linb) {
    int j = threadIdx.x;
    float s = linb[j];
#pragma unroll 8
    for (int c = 0; c < CDIM; c++) s += b2[c] * linW[c * CDIM + j];
    g_b2[j] = s;
}

// ---------------------------------------------------------------------------
// Segment mean aggregation into PERMUTED Xcat (tf32-rounded).
// One block per node, 8 warps = 8 relations; warp 0 also writes root row.
// ---------------------------------------------------------------------------
__global__ __launch_bounds__(256)
void aggregate_kernel(const float* __restrict__ feat) {
    int node = blockIdx.x;
    int r = threadIdx.x >> 5;
    int lane = threadIdx.x & 31;
    int seg = node * NREL + r;
    int beg = __ldg(&g_off[seg]);
    int end = __ldg(&g_off[seg + 1]);
    const float4* f4 = reinterpret_cast<const float4*>(feat);
    float4 a = make_float4(0.f, 0.f, 0.f, 0.f);
    int e = beg;
    for (; e + 2 <= end; e += 2) {
        int s0 = __ldg(&g_esrc[e]);
        int s1 = __ldg(&g_esrc[e + 1]);
        float4 v0 = f4[(size_t)s0 * 32 + lane];
        float4 v1 = f4[(size_t)s1 * 32 + lane];
        a.x += v0.x; a.y += v0.y; a.z += v0.z; a.w += v0.w;
        a.x += v1.x; a.y += v1.y; a.z += v1.z; a.w += v1.w;
    }
    if (e < end) {
        int s0 = __ldg(&g_esrc[e]);
        float4 v0 = f4[(size_t)s0 * 32 + lane];
        a.x += v0.x; a.y += v0.y; a.z += v0.z; a.w += v0.w;
    }
    float inv = (end > beg) ? 1.0f / (float)(end - beg) : 0.0f;
    a.x = tf32rf(a.x * inv); a.y = tf32rf(a.y * inv);
    a.z = tf32rf(a.z * inv); a.w = tf32rf(a.w * inv);
    store_perm(g_xcat + (size_t)node * KDIM + r * CDIM, lane, a);

    if (r == 0) {   // root columns: rounded, permuted copy of node's feature row
        float4 v = f4[(size_t)node * 32 + lane];
        v.x = tf32rf(v.x); v.y = tf32rf(v.y);
        v.z = tf32rf(v.z); v.w = tf32rf(v.w);
        store_perm(g_xcat + (size_t)node * KDIM + NREL * CDIM, lane, v);
    }
}

// ---------------------------------------------------------------------------
// tf32 GEMM: C[NNODES,128] = A[NNODES,1152] @ B[1152,128] + bias (opt. relu)
// A is k-permuted (fragment pairs adjacent) -> A fragments via LDS.64.
// Block tile 128x128, BK=16, 8 warps (each 64x32), mma.sync m16n8k8,
// cp.async double-buffered, conflict-free padded smem.
// ---------------------------------------------------------------------------
template <int RELU>
__global__ __launch_bounds__(256)
void gemm_kernel(const float* __restrict__ A, const float* __restrict__ B,
                 const float* __restrict__ bias, float* __restrict__ C) {
    __shared__ float As[2][128 * 20];   // rows stride 20 floats (8B-aligned pairs)
    __shared__ float Bs[2][16 * 132];

    const int tid = threadIdx.x;
    const int lane = tid & 31;
    const int warp = tid >> 5;
    const int wm = (warp & 1) * 64;
    const int wn = (warp >> 1) * 32;
    const int blockRow = blockIdx.x * 128;
    const int gid = lane >> 2;
    const int tg = lane & 3;

    float acc[4][4][4];
#pragma unroll
    for (int a = 0; a < 4; a++)
#pragma unroll
        for (int b = 0; b < 4; b++)
#pragma unroll
            for (int c = 0; c < 4; c++) acc[a][b][c] = 0.f;

    const int ar = tid >> 2;          // 0..63 (A rows ar and ar+64)
    const int ac = (tid & 3) * 4;     // float4 col in BK
    const int br = tid >> 5;          // 0..7  (B rows br and br+8)
    const int bc = (tid & 31) * 4;

    auto stage = [&](int kt, int buf) {
        int g0 = blockRow + ar;
        int g1 = g0 + 64;
        cpa16(&As[buf][ar * 20 + ac],        A + (size_t)g0 * KDIM + kt * 16 + ac, g0 < NNODES);
        cpa16(&As[buf][(ar + 64) * 20 + ac], A + (size_t)g1 * KDIM + kt * 16 + ac, g1 < NNODES);
        cpa16(&Bs[buf][br * 132 + bc],       B + (size_t)(kt * 16 + br) * CDIM + bc, true);
        cpa16(&Bs[buf][(br + 8) * 132 + bc], B + (size_t)(kt * 16 + br + 8) * CDIM + bc, true);
        asm volatile("cp.async.commit_group;");
    };

    constexpr int NKT = KDIM / 16;    // 72
    stage(0, 0);
    for (int kt = 0; kt < NKT; kt++) {
        int buf = kt & 1;
        if (kt + 1 < NKT) {
            stage(kt + 1, buf ^ 1);
            asm volatile("cp.async.wait_group 1;");
        } else {
            asm volatile("cp.async.wait_group 0;");
        }
        __syncthreads();

        const float* as = As[buf];
        const float* bs = Bs[buf];
#pragma unroll
        for (int ks = 0; ks < 16; ks += 8) {
            uint32_t af[4][4], bf[4][2];
#pragma unroll
            for (int mi = 0; mi < 4; mi++) {
                int r = wm + mi * 16 + gid;
                // permuted layout: pair (col tg, col tg+4) adjacent at ks + 2*tg
                uint2 p0 = *reinterpret_cast<const uint2*>(&as[r * 20 + ks + 2 * tg]);
                uint2 p1 = *reinterpret_cast<const uint2*>(&as[(r + 8) * 20 + ks + 2 * tg]);
                af[mi][0] = p0.x; af[mi][2] = p0.y;
                af[mi][1] = p1.x; af[mi][3] = p1.y;
            }
#pragma unroll
            for (int ni = 0; ni < 4; ni++) {
                int n = wn + ni * 8 + gid;
                bf[ni][0] = __float_as_uint(bs[(ks + tg) * 132 + n]);
                bf[ni][1] = __float_as_uint(bs[(ks + tg + 4) * 132 + n]);
            }
#pragma unroll
            for (int mi = 0; mi < 4; mi++)
#pragma unroll
                for (int ni = 0; ni < 4; ni++) mma8(acc[mi][ni], af[mi], bf[ni]);
        }
        __syncthreads();
    }

    // epilogue: bias (+relu), guarded float2 stores (C is normal row-major)
#pragma unroll
    for (int mi = 0; mi < 4; mi++) {
        int r0 = blockRow + wm + mi * 16 + gid;
        int r1 = r0 + 8;
#pragma unroll
        for (int ni = 0; ni < 4; ni++) {
            int col = wn + ni * 8 + tg * 2;
            float b0 = bias[col], b1 = bias[col + 1];
            float v0 = acc[mi][ni][0] + b0;
            float v1 = acc[mi][ni][1] + b1;
            float v2 = acc[mi][ni][2] + b0;
            float v3 = acc[mi][ni][3] + b1;
            if (RELU) {
                v0 = fmaxf(v0, 0.f); v1 = fmaxf(v1, 0.f);
                v2 = fmaxf(v2, 0.f); v3 = fmaxf(v3, 0.f);
            }
            if (r0 < NNODES) {
                float2 t; t.x = v0; t.y = v1;
                *reinterpret_cast<float2*>(C + (size_t)r0 * CDIM + col) = t;
            }
            if (r1 < NNODES) {
                float2 t; t.x = v2; t.y = v3;
                *reinterpret_cast<float2*>(C + (size_t)r1 * CDIM + col) = t;
            }
        }
    }
}

// ---------------------------------------------------------------------------
extern "C" void kernel_launch(void* const* d_in, const int* in_sizes, int n_in,
                              void* d_out, int out_size) {
    const float* x     = (const float*)d_in[0];
    const int*   ei    = (const int*)  d_in[1];
    const int*   et    = (const int*)  d_in[2];
    const float* W1    = (const float*)d_in[3];
    const float* root1 = (const float*)d_in[4];
    const float* b1    = (const float*)d_in[5];
    const float* W2    = (const float*)d_in[6];
    const float* root2 = (const float*)d_in[7];
    const float* b2    = (const float*)d_in[8];
    const float* linW  = (const float*)d_in[9];
    const float* linb  = (const float*)d_in[10];
    float* out = (float*)d_out;

    const int* src = ei;
    const int* dst = ei + NEDGES;

    float *p_xcat, *p_h, *p_w1, *p_w2, *p_b2;
    int* p_deg;
    cudaGetSymbolAddress((void**)&p_xcat, g_xcat);
    cudaGetSymbolAddress((void**)&p_h,    g_h);
    cudaGetSymbolAddress((void**)&p_w1,   g_w1);
    cudaGetSymbolAddress((void**)&p_w2,   g_w2);
    cudaGetSymbolAddress((void**)&p_b2,   g_b2);
    cudaGetSymbolAddress((void**)&p_deg,  g_deg);

    // CSR build (shared by both layers)
    cudaMemsetAsync(p_deg, 0, NRSEG * sizeof(int));
    hist_kernel<<<(NEDGES + 255) / 256, 256>>>(dst, et);
    scan1_kernel<<<NSCAN_BLOCKS, 256>>>();
    scan2_kernel<<<1, 512>>>();
    scan3_kernel<<<(NRSEG + 255) / 256, 256>>>();
    fill_kernel<<<(NEDGES + 255) / 256, 256>>>(src, dst, et);

    // weights (tf32 pre-rounded)
    buildw1_kernel<<<(KDIM * CDIM + 255) / 256, 256>>>(W1, root1);
    foldw2_kernel<<<KDIM, CDIM>>>(W2, root2, linW);
    foldb2_kernel<<<1, CDIM>>>(b2, linW, linb);

    const int nblk = (NNODES + 127) / 128;   // 391

    // layer 1 (relu)
    aggregate_kernel<<<NNODES, 256>>>(x);
    gemm_kernel<1><<<nblk, 256>>>(p_xcat, p_w1, b1, p_h);

    // layer 2 (final linear folded into weights)
    aggregate_kernel<<<NNODES, 256>>>(p_h);
    gemm_kernel<0><<<nblk, 256>>>(p_xcat, p_w2, p_b2, out);
}

// round 14
// speedup vs baseline: 1.0539x; 1.0539x over previous
#include <cuda_runtime.h>
#include <cstdint>
#include <cstddef>

// ---------------------------------------------------------------------------
// RGCN (2 layers): aggregate-then-transform, GEMMs folded, final lin folded.
// Round-14:
//   - REVERT permuted Xcat (R13 regression: scattered agg stores) -> float4 rows
//   - REVERT launch_bounds to (256)
//   - CSR build replaced by padded-slot lists: memset(cnt) + one fill kernel
//     (removes hist + 3 scan kernels; launch order now puts gemm1 at kernel #6
//      so ncu -s 5 -c 1 profiles the heavy GEMM next round)
//   - keep: producer-side tf32 rounding, folded root copy, agg unroll x2
// tcgen05 unavailable: harness PTX targets sm_103 (no 'a').
// ---------------------------------------------------------------------------

#define NNODES 50000
#define NEDGES 1000000
#define CDIM   128
#define NREL   8
#define NRSEG  (NNODES * NREL)          // 400000 segments
#define KDIM   (CDIM * (NREL + 1))      // 1152
#define PAD    32                       // max edges kept per (node,rel); Poisson(2.5) max ~15

// ---- scratch (device globals; no runtime allocation allowed) ----
__device__ int   g_cnt[NRSEG];
__device__ int   g_slot[(size_t)NRSEG * PAD];                    // 51.2 MB
__device__ __align__(256) float g_xcat[(size_t)NNODES * KDIM];   // 230.4 MB
__device__ __align__(256) float g_h[(size_t)NNODES * CDIM];      // 25.6 MB
__device__ __align__(256) float g_w1[KDIM * CDIM];
__device__ __align__(256) float g_w2[KDIM * CDIM];
__device__ __align__(16)  float g_b2[CDIM];

// ---------------------------------------------------------------------------
// helpers
// ---------------------------------------------------------------------------
__device__ __forceinline__ float tf32rf(float x) {   // round-to-nearest tf32
    uint32_t u;
    asm("cvt.rna.tf32.f32 %0, %1;" : "=r"(u) : "f"(x));
    return __uint_as_float(u);
}

__device__ __forceinline__ void cpa16(void* smem, const void* gmem, bool pred) {
    uint32_t s = (uint32_t)__cvta_generic_to_shared(smem);
    int sz = pred ? 16 : 0;
    asm volatile("cp.async.cg.shared.global [%0], [%1], 16, %2;\n"
                 :: "r"(s), "l"(gmem), "r"(sz));
}

__device__ __forceinline__ void mma8(float* c, const uint32_t* a, const uint32_t* b) {
    asm volatile(
        "mma.sync.aligned.m16n8k8.row.col.f32.tf32.tf32.f32 "
        "{%0,%1,%2,%3}, {%4,%5,%6,%7}, {%8,%9}, {%0,%1,%2,%3};"
        : "+f"(c[0]), "+f"(c[1]), "+f"(c[2]), "+f"(c[3])
        : "r"(a[0]), "r"(a[1]), "r"(a[2]), "r"(a[3]), "r"(b[0]), "r"(b[1]));
}

// ---------------------------------------------------------------------------
// Edge-list build: padded slots, one pass (cnt zeroed by memsetAsync)
// ---------------------------------------------------------------------------
__global__ void fill_kernel(const int* __restrict__ src, const int* __restrict__ dst,
                            const int* __restrict__ et) {
    int e = blockIdx.x * blockDim.x + threadIdx.x;
    if (e >= NEDGES) return;
    int seg = dst[e] * NREL + et[e];
    int pos = atomicAdd(&g_cnt[seg], 1);
    if (pos < PAD) g_slot[(size_t)seg * PAD + pos] = src[e];
}

// ---------------------------------------------------------------------------
// Weight builds (tf32 pre-rounded; [k][n] layout)
// ---------------------------------------------------------------------------
__global__ void buildw1_kernel(const float* __restrict__ W1, const float* __restrict__ root1) {
    int i = blockIdx.x * blockDim.x + threadIdx.x;
    if (i >= KDIM * CDIM) return;
    const int cut = NREL * CDIM * CDIM;
    float v = (i < cut) ? W1[i] : root1[i - cut];
    g_w1[i] = tf32rf(v);
}

__global__ void foldw2_kernel(const float* __restrict__ W2, const float* __restrict__ root2,
                              const float* __restrict__ linW) {
    __shared__ float rs[CDIM];
    int k = blockIdx.x;
    int j = threadIdx.x;
    const float* row = (k < NREL * CDIM) ? (W2 + (size_t)k * CDIM)
                                         : (root2 + (size_t)(k - NREL * CDIM) * CDIM);
    rs[j] = row[j];
    __syncthreads();
    float s = 0.f;
#pragma unroll 8
    for (int c = 0; c < CDIM; c++) s += rs[c] * linW[c * CDIM + j];
    g_w2[(size_t)k * CDIM + j] = tf32rf(s);
}

__global__ void foldb2_kernel(const float* __restrict__ b2, const float* __restrict__ linW,
                              const float* __restrict__ linb) {
    int j = threadIdx.x;
    float s = linb[j];
#pragma unroll 8
    for (int c = 0; c < CDIM; c++) s += b2[c] * linW[c * CDIM + j];
    g_b2[j] = s;
}

// ---------------------------------------------------------------------------
// Segment mean aggregation into Xcat (tf32-rounded), one block per node,
// 8 warps = 8 relations; warp 0 also writes the rounded root row.
// ---------------------------------------------------------------------------
__global__ __launch_bounds__(256)
void aggregate_kernel(const float* __restrict__ feat) {
    int node = blockIdx.x;
    int r = threadIdx.x >> 5;
    int lane = threadIdx.x & 31;
    int seg = node * NREL + r;
    int cnt = __ldg(&g_cnt[seg]);
    int n = cnt < PAD ? cnt : PAD;
    const int* sl = g_slot + (size_t)seg * PAD;
    const float4* f4 = reinterpret_cast<const float4*>(feat);
    float4 a = make_float4(0.f, 0.f, 0.f, 0.f);
    int e = 0;
    for (; e + 2 <= n; e += 2) {
        int s0 = __ldg(&sl[e]);
        int s1 = __ldg(&sl[e + 1]);
        float4 v0 = f4[(size_t)s0 * 32 + lane];
        float4 v1 = f4[(size_t)s1 * 32 + lane];
        a.x += v0.x; a.y += v0.y; a.z += v0.z; a.w += v0.w;
        a.x += v1.x; a.y += v1.y; a.z += v1.z; a.w += v1.w;
    }
    if (e < n) {
        int s0 = __ldg(&sl[e]);
        float4 v0 = f4[(size_t)s0 * 32 + lane];
        a.x += v0.x; a.y += v0.y; a.z += v0.z; a.w += v0.w;
    }
    float inv = (cnt > 0) ? 1.0f / (float)cnt : 0.0f;
    a.x = tf32rf(a.x * inv); a.y = tf32rf(a.y * inv);
    a.z = tf32rf(a.z * inv); a.w = tf32rf(a.w * inv);
    reinterpret_cast<float4*>(g_xcat + (size_t)node * KDIM + r * CDIM)[lane] = a;

    if (r == 0) {   // root columns: rounded copy of this node's feature row
        float4 v = f4[(size_t)node * 32 + lane];
        v.x = tf32rf(v.x); v.y = tf32rf(v.y);
        v.z = tf32rf(v.z); v.w = tf32rf(v.w);
        reinterpret_cast<float4*>(g_xcat + (size_t)node * KDIM + NREL * CDIM)[lane] = v;
    }
}

// ---------------------------------------------------------------------------
// tf32 GEMM: C[NNODES,128] = A[NNODES,1152] @ B[1152,128] + bias (opt. relu)
// Operands pre-rounded to tf32 -> no cvt in the hot loop.
// Block tile 128x128, BK=16, 8 warps (each 64x32), mma.sync m16n8k8,
// cp.async double-buffered, conflict-free padded smem.
// ---------------------------------------------------------------------------
template <int RELU>
__global__ __launch_bounds__(256)
void gemm_kernel(const float* __restrict__ A, const float* __restrict__ B,
                 const float* __restrict__ bias, float* __restrict__ C) {
    __shared__ float As[2][128 * 20];
    __shared__ float Bs[2][16 * 132];

    const int tid = threadIdx.x;
    const int lane = tid & 31;
    const int warp = tid >> 5;
    const int wm = (warp & 1) * 64;
    const int wn = (warp >> 1) * 32;
    const int blockRow = blockIdx.x * 128;
    const int gid = lane >> 2;
    const int tg = lane & 3;

    float acc[4][4][4];
#pragma unroll
    for (int a = 0; a < 4; a++)
#pragma unroll
        for (int b = 0; b < 4; b++)
#pragma unroll
            for (int c = 0; c < 4; c++) acc[a][b][c] = 0.f;

    const int ar = tid >> 2;          // 0..63 (A rows ar and ar+64)
    const int ac = (tid & 3) * 4;     // float4 col in BK
    const int br = tid >> 5;          // 0..7  (B rows br and br+8)
    const int bc = (tid & 31) * 4;

    auto stage = [&](int kt, int buf) {
        int g0 = blockRow + ar;
        int g1 = g0 + 64;
        cpa16(&As[buf][ar * 20 + ac],        A + (size_t)g0 * KDIM + kt * 16 + ac, g0 < NNODES);
        cpa16(&As[buf][(ar + 64) * 20 + ac], A + (size_t)g1 * KDIM + kt * 16 + ac, g1 < NNODES);
        cpa16(&Bs[buf][br * 132 + bc],       B + (size_t)(kt * 16 + br) * CDIM + bc, true);
        cpa16(&Bs[buf][(br + 8) * 132 + bc], B + (size_t)(kt * 16 + br + 8) * CDIM + bc, true);
        asm volatile("cp.async.commit_group;");
    };

    constexpr int NKT = KDIM / 16;    // 72
    stage(0, 0);
    for (int kt = 0; kt < NKT; kt++) {
        int buf = kt & 1;
        if (kt + 1 < NKT) {
            stage(kt + 1, buf ^ 1);
            asm volatile("cp.async.wait_group 1;");
        } else {
            asm volatile("cp.async.wait_group 0;");
        }
        __syncthreads();

        const float* as = As[buf];
        const float* bs = Bs[buf];
#pragma unroll
        for (int ks = 0; ks < 16; ks += 8) {
            uint32_t af[4][4], bf[4][2];
#pragma unroll
            for (int mi = 0; mi < 4; mi++) {
                int r = wm + mi * 16 + gid;
                af[mi][0] = __float_as_uint(as[r * 20 + ks + tg]);
                af[mi][1] = __float_as_uint(as[(r + 8) * 20 + ks + tg]);
                af[mi][2] = __float_as_uint(as[r * 20 + ks + tg + 4]);
                af[mi][3] = __float_as_uint(as[(r + 8) * 20 + ks + tg + 4]);
            }
#pragma unroll
            for (int ni = 0; ni < 4; ni++) {
                int n = wn + ni * 8 + gid;
                bf[ni][0] = __float_as_uint(bs[(ks + tg) * 132 + n]);
                bf[ni][1] = __float_as_uint(bs[(ks + tg + 4) * 132 + n]);
            }
#pragma unroll
            for (int mi = 0; mi < 4; mi++)
#pragma unroll
                for (int ni = 0; ni < 4; ni++) mma8(acc[mi][ni], af[mi], bf[ni]);
        }
        __syncthreads();
    }

    // epilogue: bias (+relu), guarded float2 stores
#pragma unroll
    for (int mi = 0; mi < 4; mi++) {
        int r0 = blockRow + wm + mi * 16 + gid;
        int r1 = r0 + 8;
#pragma unroll
        for (int ni = 0; ni < 4; ni++) {
            int col = wn + ni * 8 + tg * 2;
            float b0 = bias[col], b1 = bias[col + 1];
            float v0 = acc[mi][ni][0] + b0;
            float v1 = acc[mi][ni][1] + b1;
            float v2 = acc[mi][ni][2] + b0;
            float v3 = acc[mi][ni][3] + b1;
            if (RELU) {
                v0 = fmaxf(v0, 0.f); v1 = fmaxf(v1, 0.f);
                v2 = fmaxf(v2, 0.f); v3 = fmaxf(v3, 0.f);
            }
            if (r0 < NNODES) {
                float2 t; t.x = v0; t.y = v1;
                *reinterpret_cast<float2*>(C + (size_t)r0 * CDIM + col) = t;
            }
            if (r1 < NNODES) {
                float2 t; t.x = v2; t.y = v3;
                *reinterpret_cast<float2*>(C + (size_t)r1 * CDIM + col) = t;
            }
        }
    }
}

// ---------------------------------------------------------------------------
extern "C" void kernel_launch(void* const* d_in, const int* in_sizes, int n_in,
                              void* d_out, int out_size) {
    const float* x     = (const float*)d_in[0];
    const int*   ei    = (const int*)  d_in[1];
    const int*   et    = (const int*)  d_in[2];
    const float* W1    = (const float*)d_in[3];
    const float* root1 = (const float*)d_in[4];
    const float* b1    = (const float*)d_in[5];
    const float* W2    = (const float*)d_in[6];
    const float* root2 = (const float*)d_in[7];
    const float* b2    = (const float*)d_in[8];
    const float* linW  = (const float*)d_in[9];
    const float* linb  = (const float*)d_in[10];
    float* out = (float*)d_out;

    const int* src = ei;
    const int* dst = ei + NEDGES;

    float *p_xcat, *p_h, *p_w1, *p_w2, *p_b2;
    int* p_cnt;
    cudaGetSymbolAddress((void**)&p_xcat, g_xcat);
    cudaGetSymbolAddress((void**)&p_h,    g_h);
    cudaGetSymbolAddress((void**)&p_w1,   g_w1);
    cudaGetSymbolAddress((void**)&p_w2,   g_w2);
    cudaGetSymbolAddress((void**)&p_b2,   g_b2);
    cudaGetSymbolAddress((void**)&p_cnt,  g_cnt);

    // edge-list build (padded slots; shared by both layers)
    cudaMemsetAsync(p_cnt, 0, NRSEG * sizeof(int));
    fill_kernel<<<(NEDGES + 255) / 256, 256>>>(src, dst, et);          // launch 1

    // weights (tf32 pre-rounded)
    buildw1_kernel<<<(KDIM * CDIM + 255) / 256, 256>>>(W1, root1);     // launch 2
    foldw2_kernel<<<KDIM, CDIM>>>(W2, root2, linW);                    // launch 3
    foldb2_kernel<<<1, CDIM>>>(b2, linW, linb);                        // launch 4

    const int nblk = (NNODES + 127) / 128;   // 391

    // layer 1 (relu)
    aggregate_kernel<<<NNODES, 256>>>(x);                              // launch 5
    gemm_kernel<1><<<nblk, 256>>>(p_xcat, p_w1, b1, p_h);              // launch 6 <- ncu -s 5

    // layer 2 (final linear folded into weights)
    aggregate_kernel<<<NNODES, 256>>>(p_h);
    gemm_kernel<0><<<nblk, 256>>>(p_xcat, p_w2, p_b2, out);
}

// round 15
// speedup vs baseline: 1.0886x; 1.0329x over previous
#include <cuda_runtime.h>
#include <cstdint>
#include <cstddef>

// ---------------------------------------------------------------------------
// RGCN (2 layers): aggregate-then-transform, GEMMs folded, final lin folded.
// Round-15 consolidation:
//   - CSR build restored (R12 proven; padded slots of R14 were -14us)
//   - NO memset: scan3 re-zeroes g_deg after scan1 consumed it (next call
//     starts clean; device globals are zero-init at load) -> one less op
//   - ALL weight prep merged into ONE heterogeneous-grid kernel; the b2 fold
//     is block-parallel (was a 12.7us single-block serial straggler)
//   - launch order puts agg1 at kernel #6 so ncu -s 5 -c 1 profiles it
//   - keep: producer-side tf32 rounding, folded root copy, agg unroll x2,
//     gemm launch_bounds(256), mma.sync m16n8k8 tf32 (tcgen05 not available
//     at the harness's sm_103 PTX target)
// ---------------------------------------------------------------------------

#define NNODES 50000
#define NEDGES 1000000
#define CDIM   128
#define NREL   8
#define NRSEG  (NNODES * NREL)          // 400000 segments
#define KDIM   (CDIM * (NREL + 1))      // 1152
#define SCAN_CHUNK 1024
#define NSCAN_BLOCKS ((NRSEG + SCAN_CHUNK - 1) / SCAN_CHUNK)   // 391

// ---- scratch (device globals; no runtime allocation allowed) ----
__device__ int   g_deg[NRSEG];          // zero at load; re-zeroed by scan3 each call
__device__ int   g_off[NRSEG + 1];
__device__ int   g_cur[NRSEG];
__device__ int   g_bsum[512];
__device__ int   g_bscan[512];
__device__ int   g_esrc[NEDGES];
__device__ __align__(256) float g_xcat[(size_t)NNODES * KDIM];   // 230.4 MB
__device__ __align__(256) float g_h[(size_t)NNODES * CDIM];      // 25.6 MB
__device__ __align__(256) float g_w1[KDIM * CDIM];
__device__ __align__(256) float g_w2[KDIM * CDIM];
__device__ __align__(16)  float g_b2[CDIM];

// ---------------------------------------------------------------------------
// helpers
// ---------------------------------------------------------------------------
__device__ __forceinline__ float tf32rf(float x) {   // round-to-nearest tf32
    uint32_t u;
    asm("cvt.rna.tf32.f32 %0, %1;" : "=r"(u) : "f"(x));
    return __uint_as_float(u);
}

__device__ __forceinline__ void cpa16(void* smem, const void* gmem, bool pred) {
    uint32_t s = (uint32_t)__cvta_generic_to_shared(smem);
    int sz = pred ? 16 : 0;
    asm volatile("cp.async.cg.shared.global [%0], [%1], 16, %2;\n"
                 :: "r"(s), "l"(gmem), "r"(sz));
}

__device__ __forceinline__ void mma8(float* c, const uint32_t* a, const uint32_t* b) {
    asm volatile(
        "mma.sync.aligned.m16n8k8.row.col.f32.tf32.tf32.f32 "
        "{%0,%1,%2,%3}, {%4,%5,%6,%7}, {%8,%9}, {%0,%1,%2,%3};"
        : "+f"(c[0]), "+f"(c[1]), "+f"(c[2]), "+f"(c[3])
        : "r"(a[0]), "r"(a[1]), "r"(a[2]), "r"(a[3]), "r"(b[0]), "r"(b[1]));
}

// ---------------------------------------------------------------------------
// CSR build (R12 proven; no separate zeroing kernel)
// ---------------------------------------------------------------------------
__global__ void hist_kernel(const int* __restrict__ dst, const int* __restrict__ et) {
    int e = blockIdx.x * blockDim.x + threadIdx.x;
    if (e >= NEDGES) return;
    atomicAdd(&g_deg[dst[e] * NREL + et[e]], 1);
}

__global__ void scan1_kernel() {
    __shared__ int sh[256];
    int t = threadIdx.x;
    int base = blockIdx.x * SCAN_CHUNK + t * 4;
    int v[4];
    int s = 0;
#pragma unroll
    for (int j = 0; j < 4; j++) {
        int idx = base + j;
        v[j] = (idx < NRSEG) ? g_deg[idx] : 0;
        s += v[j];
    }
    sh[t] = s;
    __syncthreads();
    for (int off = 1; off < 256; off <<= 1) {
        int x = (t >= off) ? sh[t - off] : 0;
        __syncthreads();
        sh[t] += x;
        __syncthreads();
    }
    int incl = sh[t];
    int run = incl - s;
    if (t == 255) g_bsum[blockIdx.x] = incl;
#pragma unroll
    for (int j = 0; j < 4; j++) {
        int idx = base + j;
        if (idx < NRSEG) g_off[idx] = run;
        run += v[j];
    }
}

__global__ void scan2_kernel() {
    __shared__ int sh[512];
    int t = threadIdx.x;
    int v = (t < NSCAN_BLOCKS) ? g_bsum[t] : 0;
    sh[t] = v;
    __syncthreads();
    for (int off = 1; off < 512; off <<= 1) {
        int x = (t >= off) ? sh[t - off] : 0;
        __syncthreads();
        sh[t] += x;
        __syncthreads();
    }
    if (t < NSCAN_BLOCKS) g_bscan[t] = sh[t] - v;
    if (t == NSCAN_BLOCKS - 1) g_off[NRSEG] = sh[t];
}

__global__ void scan3_kernel() {
    int i = blockIdx.x * blockDim.x + threadIdx.x;
    if (i >= NRSEG) return;
    int v = g_off[i] + g_bscan[i / SCAN_CHUNK];
    g_off[i] = v;
    g_cur[i] = v;
    g_deg[i] = 0;          // reset for the NEXT kernel_launch call (deterministic)
}

__global__ void fill_kernel(const int* __restrict__ src, const int* __restrict__ dst,
                            const int* __restrict__ et) {
    int e = blockIdx.x * blockDim.x + threadIdx.x;
    if (e >= NEDGES) return;
    int seg = dst[e] * NREL + et[e];
    int pos = atomicAdd(&g_cur[seg], 1);
    g_esrc[pos] = src[e];
}

// ---------------------------------------------------------------------------
// Merged weight prep: ONE launch, heterogeneous blocks (all tf32 pre-rounded)
//   blocks [0, 288):            W1cat float4 copy (288*128*4 = 147456 floats)
//   blocks [288, 288+1152):     W2cat' fold: row k of vstack(W2,root2) @ linW
//   blocks [288+1152, +128):    b2' fold: one block per output j (block reduce)
// ---------------------------------------------------------------------------
#define W1_BLOCKS 288
#define WPREP_GRID (W1_BLOCKS + KDIM + CDIM)   // 288 + 1152 + 128 = 1568

__global__ __launch_bounds__(128)
void weights_kernel(const float* __restrict__ W1, const float* __restrict__ root1,
                    const float* __restrict__ W2, const float* __restrict__ root2,
                    const float* __restrict__ linW,
                    const float* __restrict__ b2in, const float* __restrict__ linb) {
    int b = blockIdx.x;
    int t = threadIdx.x;

    if (b < W1_BLOCKS) {
        // W1cat copy (float4): cut at NREL*CDIM*CDIM floats (divisible by 4)
        int i4 = b * 128 + t;
        const int cut4 = NREL * CDIM * CDIM / 4;
        float4 v = (i4 < cut4)
                 ? reinterpret_cast<const float4*>(W1)[i4]
                 : reinterpret_cast<const float4*>(root1)[i4 - cut4];
        v.x = tf32rf(v.x); v.y = tf32rf(v.y); v.z = tf32rf(v.z); v.w = tf32rf(v.w);
        reinterpret_cast<float4*>(g_w1)[i4] = v;
    } else if (b < W1_BLOCKS + KDIM) {
        // W2cat'[k][j] = sum_c vstack(W2,root2)[k][c] * linW[c][j]
        __shared__ float rs[CDIM];
        int k = b - W1_BLOCKS;
        const float* row = (k < NREL * CDIM) ? (W2 + (size_t)k * CDIM)
                                             : (root2 + (size_t)(k - NREL * CDIM) * CDIM);
        rs[t] = row[t];
        __syncthreads();
        float s = 0.f;
#pragma unroll 8
        for (int c = 0; c < CDIM; c++) s += rs[c] * linW[c * CDIM + t];
        g_w2[(size_t)k * CDIM + t] = tf32rf(s);
    } else {
        // b2'[j] = linb[j] + sum_c b2in[c]*linW[c][j]  (block per j, reduce over c)
        __shared__ float red[CDIM];
        int j = b - W1_BLOCKS - KDIM;
        red[t] = b2in[t] * linW[t * CDIM + j];
        __syncthreads();
        for (int off = 64; off > 0; off >>= 1) {
            if (t < off) red[t] += red[t + off];
            __syncthreads();
        }
        if (t == 0) g_b2[j] = linb[j] + red[0];
    }
}

// ---------------------------------------------------------------------------
// Segment mean aggregation into Xcat (tf32-rounded), one block per node,
// 8 warps = 8 relations; warp 0 also writes the rounded root row.
// ---------------------------------------------------------------------------
__global__ __launch_bounds__(256)
void aggregate_kernel(const float* __restrict__ feat) {
    int node = blockIdx.x;
    int r = threadIdx.x >> 5;
    int lane = threadIdx.x & 31;
    int seg = node * NREL + r;
    int beg = __ldg(&g_off[seg]);
    int end = __ldg(&g_off[seg + 1]);
    const float4* f4 = reinterpret_cast<const float4*>(feat);
    float4 a = make_float4(0.f, 0.f, 0.f, 0.f);
    int e = beg;
    for (; e + 2 <= end; e += 2) {
        int s0 = __ldg(&g_esrc[e]);
        int s1 = __ldg(&g_esrc[e + 1]);
        float4 v0 = f4[(size_t)s0 * 32 + lane];
        float4 v1 = f4[(size_t)s1 * 32 + lane];
        a.x += v0.x; a.y += v0.y; a.z += v0.z; a.w += v0.w;
        a.x += v1.x; a.y += v1.y; a.z += v1.z; a.w += v1.w;
    }
    if (e < end) {
        int s0 = __ldg(&g_esrc[e]);
        float4 v0 = f4[(size_t)s0 * 32 + lane];
        a.x += v0.x; a.y += v0.y; a.z += v0.z; a.w += v0.w;
    }
    float inv = (end > beg) ? 1.0f / (float)(end - beg) : 0.0f;
    a.x = tf32rf(a.x * inv); a.y = tf32rf(a.y * inv);
    a.z = tf32rf(a.z * inv); a.w = tf32rf(a.w * inv);
    reinterpret_cast<float4*>(g_xcat + (size_t)node * KDIM + r * CDIM)[lane] = a;

    if (r == 0) {   // root columns: rounded copy of this node's feature row
        float4 v = f4[(size_t)node * 32 + lane];
        v.x = tf32rf(v.x); v.y = tf32rf(v.y);
        v.z = tf32rf(v.z); v.w = tf32rf(v.w);
        reinterpret_cast<float4*>(g_xcat + (size_t)node * KDIM + NREL * CDIM)[lane] = v;
    }
}

// ---------------------------------------------------------------------------
// tf32 GEMM: C[NNODES,128] = A[NNODES,1152] @ B[1152,128] + bias (opt. relu)
// Operands pre-rounded to tf32 -> no cvt in the hot loop.
// Block tile 128x128, BK=16, 8 warps (each 64x32), mma.sync m16n8k8,
// cp.async double-buffered, conflict-free padded smem.
// ---------------------------------------------------------------------------
template <int RELU>
__global__ __launch_bounds__(256)
void gemm_kernel(const float* __restrict__ A, const float* __restrict__ B,
                 const float* __restrict__ bias, float* __restrict__ C) {
    __shared__ float As[2][128 * 20];
    __shared__ float Bs[2][16 * 132];

    const int tid = threadIdx.x;
    const int lane = tid & 31;
    const int warp = tid >> 5;
    const int wm = (warp & 1) * 64;
    const int wn = (warp >> 1) * 32;
    const int blockRow = blockIdx.x * 128;
    const int gid = lane >> 2;
    const int tg = lane & 3;

    float acc[4][4][4];
#pragma unroll
    for (int a = 0; a < 4; a++)
#pragma unroll
        for (int b = 0; b < 4; b++)
#pragma unroll
            for (int c = 0; c < 4; c++) acc[a][b][c] = 0.f;

    const int ar = tid >> 2;          // 0..63 (A rows ar and ar+64)
    const int ac = (tid & 3) * 4;     // float4 col in BK
    const int br = tid >> 5;          // 0..7  (B rows br and br+8)
    const int bc = (tid & 31) * 4;

    auto stage = [&](int kt, int buf) {
        int g0 = blockRow + ar;
        int g1 = g0 + 64;
        cpa16(&As[buf][ar * 20 + ac],        A + (size_t)g0 * KDIM + kt * 16 + ac, g0 < NNODES);
        cpa16(&As[buf][(ar + 64) * 20 + ac], A + (size_t)g1 * KDIM + kt * 16 + ac, g1 < NNODES);
        cpa16(&Bs[buf][br * 132 + bc],       B + (size_t)(kt * 16 + br) * CDIM + bc, true);
        cpa16(&Bs[buf][(br + 8) * 132 + bc], B + (size_t)(kt * 16 + br + 8) * CDIM + bc, true);
        asm volatile("cp.async.commit_group;");
    };

    constexpr int NKT = KDIM / 16;    // 72
    stage(0, 0);
    for (int kt = 0; kt < NKT; kt++) {
        int buf = kt & 1;
        if (kt + 1 < NKT) {
            stage(kt + 1, buf ^ 1);
            asm volatile("cp.async.wait_group 1;");
        } else {
            asm volatile("cp.async.wait_group 0;");
        }
        __syncthreads();

        const float* as = As[buf];
        const float* bs = Bs[buf];
#pragma unroll
        for (int ks = 0; ks < 16; ks += 8) {
            uint32_t af[4][4], bf[4][2];
#pragma unroll
            for (int mi = 0; mi < 4; mi++) {
                int r = wm + mi * 16 + gid;
                af[mi][0] = __float_as_uint(as[r * 20 + ks + tg]);
                af[mi][1] = __float_as_uint(as[(r + 8) * 20 + ks + tg]);
                af[mi][2] = __float_as_uint(as[r * 20 + ks + tg + 4]);
                af[mi][3] = __float_as_uint(as[(r + 8) * 20 + ks + tg + 4]);
            }
#pragma unroll
            for (int ni = 0; ni < 4; ni++) {
                int n = wn + ni * 8 + gid;
                bf[ni][0] = __float_as_uint(bs[(ks + tg) * 132 + n]);
                bf[ni][1] = __float_as_uint(bs[(ks + tg + 4) * 132 + n]);
            }
#pragma unroll
            for (int mi = 0; mi < 4; mi++)
#pragma unroll
                for (int ni = 0; ni < 4; ni++) mma8(acc[mi][ni], af[mi], bf[ni]);
        }
        __syncthreads();
    }

    // epilogue: bias (+relu), guarded float2 stores
#pragma unroll
    for (int mi = 0; mi < 4; mi++) {
        int r0 = blockRow + wm + mi * 16 + gid;
        int r1 = r0 + 8;
#pragma unroll
        for (int ni = 0; ni < 4; ni++) {
            int col = wn + ni * 8 + tg * 2;
            float b0 = bias[col], b1 = bias[col + 1];
            float v0 = acc[mi][ni][0] + b0;
            float v1 = acc[mi][ni][1] + b1;
            float v2 = acc[mi][ni][2] + b0;
            float v3 = acc[mi][ni][3] + b1;
            if (RELU) {
                v0 = fmaxf(v0, 0.f); v1 = fmaxf(v1, 0.f);
                v2 = fmaxf(v2, 0.f); v3 = fmaxf(v3, 0.f);
            }
            if (r0 < NNODES) {
                float2 t; t.x = v0; t.y = v1;
                *reinterpret_cast<float2*>(C + (size_t)r0 * CDIM + col) = t;
            }
            if (r1 < NNODES) {
                float2 t; t.x = v2; t.y = v3;
                *reinterpret_cast<float2*>(C + (size_t)r1 * CDIM + col) = t;
            }
        }
    }
}

// ---------------------------------------------------------------------------
extern "C" void kernel_launch(void* const* d_in, const int* in_sizes, int n_in,
                              void* d_out, int out_size) {
    const float* x     = (const float*)d_in[0];
    const int*   ei    = (const int*)  d_in[1];
    const int*   et    = (const int*)  d_in[2];
    const float* W1    = (const float*)d_in[3];
    const float* root1 = (const float*)d_in[4];
    const float* b1    = (const float*)d_in[5];
    const float* W2    = (const float*)d_in[6];
    const float* root2 = (const float*)d_in[7];
    const float* b2    = (const float*)d_in[8];
    const float* linW  = (const float*)d_in[9];
    const float* linb  = (const float*)d_in[10];
    float* out = (float*)d_out;

    const int* src = ei;
    const int* dst = ei + NEDGES;

    float *p_xcat, *p_h, *p_w1, *p_w2, *p_b2;
    cudaGetSymbolAddress((void**)&p_xcat, g_xcat);
    cudaGetSymbolAddress((void**)&p_h,    g_h);
    cudaGetSymbolAddress((void**)&p_w1,   g_w1);
    cudaGetSymbolAddress((void**)&p_w2,   g_w2);
    cudaGetSymbolAddress((void**)&p_b2,   g_b2);

    const int nblk = (NNODES + 127) / 128;   // 391

    // CSR build (g_deg zeroed at module load / by previous call's scan3)
    hist_kernel<<<(NEDGES + 255) / 256, 256>>>(dst, et);               // 1
    scan1_kernel<<<NSCAN_BLOCKS, 256>>>();                             // 2
    scan2_kernel<<<1, 512>>>();                                        // 3
    scan3_kernel<<<(NRSEG + 255) / 256, 256>>>();                      // 4
    fill_kernel<<<(NEDGES + 255) / 256, 256>>>(src, dst, et);          // 5

    // layer 1 aggregation first (ncu -s 5 -c 1 profiles this)
    aggregate_kernel<<<NNODES, 256>>>(x);                              // 6

    // merged weight prep (independent of aggregation; before gemm1)
    weights_kernel<<<WPREP_GRID, 128>>>(W1, root1, W2, root2, linW, b2, linb);  // 7

    gemm_kernel<1><<<nblk, 256>>>(p_xcat, p_w1, b1, p_h);              // 8

    // layer 2 (final linear folded into weights)
    aggregate_kernel<<<NNODES, 256>>>(p_h);                            // 9
    gemm_kernel<0><<<nblk, 256>>>(p_xcat, p_w2, p_b2, out);            // 10
}